// round 15
// baseline (speedup 1.0000x reference)
#include <cuda_runtime.h>
#include <cstdint>

// Problem constants
#define B_   4
#define N_   24
#define C_   256
#define H_   100
#define W_   100
#define OUT_ 7
#define P_   276                      // N*(N-1)/2
#define CH_  (C_ * OUT_ * OUT_)       // 12544 floats per full [C,7,7] chunk
#define HCH_ (CH_ / 2)                // 6272 floats per half-channel chunk
#define HW_  (H_ * W_)
#define SCALE_ 0.25f
#define NROIS_ (N_ + P_)              // 300 rois per batch
#define NV_   (HCH_ / 4)              // 1568 float4 per half tile
#define RPT_  7                       // ceil(1568/256) staging slots

#define HWT_  313                     // ceil(HW/32) hw tiles
#define TPB_  (HWT_ * (C_ / 32))      // 2504 transpose CTAs per batch
#define NT_   (TPB_ * B_)             // 10016 transpose CTAs total
#define NR_   (2 * B_ * NROIS_)       // 2400 roi CTAs

// NHWC scratch + per-batch transpose completion counters (zero-initialized).
__device__ float g_nhwc[(size_t)B_ * HW_ * C_];
__device__ unsigned int g_done[B_];

__device__ __forceinline__ void stcs4(float4* p, float4 v) {
    asm volatile("st.global.cs.v4.f32 [%0], {%1,%2,%3,%4};"
                 :: "l"(p), "f"(v.x), "f"(v.y), "f"(v.z), "f"(v.w) : "memory");
}

// ---------------------------------------------------------------------------
// Phase-B helper: one bin; loads all 16 taps into locals first (MLP 16).
// ---------------------------------------------------------------------------
__device__ __forceinline__ float4 bin_taps(
    int bin, const float4* __restrict__ feat,
    const int* sy0, const int* sy1, const int* sx0, const int* sx1,
    const float* sly, const float* shy, const float* slx, const float* shx)
{
    const int py = bin / OUT_;
    const int px = bin - py * OUT_;

    int   rows[4];  float wy[4];
    int   cols[4];  float wx[4];
#pragma unroll
    for (int s = 0; s < 2; ++s) {
        const int yi = 2 * py + s;
        rows[2 * s]     = sy0[yi] * W_;
        rows[2 * s + 1] = sy1[yi] * W_;
        wy[2 * s]       = shy[yi];
        wy[2 * s + 1]   = sly[yi];
        const int xi = 2 * px + s;
        cols[2 * s]     = sx0[xi];
        cols[2 * s + 1] = sx1[xi];
        wx[2 * s]       = shx[xi];
        wx[2 * s + 1]   = slx[xi];
    }

    float4 f[16];
#pragma unroll
    for (int ys = 0; ys < 2; ++ys)
#pragma unroll
        for (int yt = 0; yt < 2; ++yt)
#pragma unroll
            for (int xs = 0; xs < 2; ++xs)
#pragma unroll
                for (int xt = 0; xt < 2; ++xt)
                    f[((ys * 2 + yt) * 2 + xs) * 2 + xt] =
                        feat[(size_t)(rows[2 * ys + yt] + cols[2 * xs + xt]) * 64];

    float4 acc = make_float4(0.f, 0.f, 0.f, 0.f);
#pragma unroll
    for (int ys = 0; ys < 2; ++ys)
#pragma unroll
        for (int yt = 0; yt < 2; ++yt)
#pragma unroll
            for (int xs = 0; xs < 2; ++xs)
#pragma unroll
                for (int xt = 0; xt < 2; ++xt) {
                    const float w = wy[2 * ys + yt] * wx[2 * xs + xt];
                    const float4 v = f[((ys * 2 + yt) * 2 + xs) * 2 + xt];
                    acc.x += w * v.x;
                    acc.y += w * v.y;
                    acc.z += w * v.z;
                    acc.w += w * v.w;
                }
    return acc;
}

// ---------------------------------------------------------------------------
// FUSED kernel. Blocks [0, NT_): transpose (batch-major). Blocks [NT_, +NR_):
// roi (batch-major; per batch: 24 objects then 276 unions, x2 channel halves).
// Roi blocks spin on g_done[b] (per-batch transpose completion) so roi work
// for batch b starts as soon as batch b's features are transposed.
// In-order dispatch: all transpose blocks precede roi blocks -> no deadlock.
// ---------------------------------------------------------------------------
__global__ __launch_bounds__(256, 3) void fused_kernel(
    const float* __restrict__ features,  // [B,C,H,W]
    const float* __restrict__ boxes,     // [B,N,4]
    float* __restrict__ out)             // [B*P, 3, C, 7, 7]
{
    __shared__ __align__(16) float smem_raw[HCH_];  // roi: pooled; transpose: tile
    __shared__ int   sy0[14], sy1[14], sx0[14], sx1[14];
    __shared__ float sly[14], shy[14], slx[14], shx[14];

    const int bid = blockIdx.x;
    const int tid = threadIdx.x;

    // ---------------- Transpose path ----------------
    if (bid < NT_) {
        float (*tile)[33] = reinterpret_cast<float (*)[33]>(smem_raw);
        const int b   = bid / TPB_;
        const int rem = bid - b * TPB_;
        const int c0  = (rem / HWT_) * 32;
        const int hw0 = (rem - (rem / HWT_) * HWT_) * 32;
        const int tx = tid & 31, ty = tid >> 5;

        const float* src = features + (size_t)b * C_ * HW_;
#pragma unroll
        for (int i = 0; i < 32; i += 8) {
            const int c  = c0 + ty + i;
            const int hw = hw0 + tx;
            float v = 0.0f;
            if (hw < HW_) v = src[(size_t)c * HW_ + hw];
            tile[ty + i][tx] = v;
        }
        __syncthreads();

        const int tx8 = tid & 7;
        const int tyy = tid >> 3;
        const int hw  = hw0 + tyy;
        if (hw < HW_) {
            float4 v;
            v.x = tile[4 * tx8 + 0][tyy];
            v.y = tile[4 * tx8 + 1][tyy];
            v.z = tile[4 * tx8 + 2][tyy];
            v.w = tile[4 * tx8 + 3][tyy];
            float* dst = g_nhwc + (size_t)b * HW_ * C_;
            *reinterpret_cast<float4*>(&dst[(size_t)hw * C_ + c0 + 4 * tx8]) = v;
        }
        __syncthreads();
        if (tid == 0) {
            __threadfence();
            atomicAdd(&g_done[b], 1u);
        }
        return;
    }

    // ---------------- RoI path ----------------
    float* pooled = smem_raw;
    const int rid   = bid - NT_;
    const int b     = rid / (2 * NROIS_);
    const int local = rid - b * (2 * NROIS_);
    const int m     = local >> 1;    // 0..299: <N_ object, else union m-N_
    const int half  = local & 1;

    // Sample tables (independent of features — compute before the spin).
    if (tid < 28) {
        float x1, y1, x2, y2;
        if (m < N_) {
            const float* bx = boxes + ((size_t)b * N_ + m) * 4;
            x1 = bx[0]; y1 = bx[1]; x2 = bx[2]; y2 = bx[3];
        } else {
            int p = m - N_;
            int i = 0, rem2 = p, cnt = N_ - 1;
            while (rem2 >= cnt) { rem2 -= cnt; ++i; --cnt; }
            const int j = i + 1 + rem2;
            const float* ba = boxes + ((size_t)b * N_ + i) * 4;
            const float* bb = boxes + ((size_t)b * N_ + j) * 4;
            x1 = fminf(ba[0], bb[0]);
            y1 = fminf(ba[1], bb[1]);
            x2 = fmaxf(ba[2], bb[2]);
            y2 = fmaxf(ba[3], bb[3]);
        }
        const int  d   = tid % 14;
        const bool isY = (tid >= 14);
        const float c1 = (isY ? y1 : x1) * SCALE_;
        const float c2 = (isY ? y2 : x2) * SCALE_;
        const float sz  = fmaxf(c2 - c1, 1.0f);
        const float bsz = sz * (1.0f / OUT_);
        const float g = (float)(d >> 1) + ((float)(d & 1) + 0.5f) * 0.5f;
        const float X = c1 + g * bsz;
        const int   lim = isY ? H_ : W_;
        const bool  valid = (X > -1.0f) && (X < (float)lim);
        const float Xc  = fminf(fmaxf(X, 0.0f), (float)(lim - 1));
        const float x0f = floorf(Xc);
        float lx = Xc - x0f;
        float hx = 1.0f - lx;
        if (!valid) { lx = 0.0f; hx = 0.0f; }
        const int t0 = (int)x0f;
        const int t1 = min(t0 + 1, lim - 1);
        if (isY) { sy0[d] = t0; sy1[d] = t1; sly[d] = lx; shy[d] = hx; }
        else     { sx0[d] = t0; sx1[d] = t1; slx[d] = lx; shx[d] = hx; }
    }

    // Wait for this batch's transpose to complete.
    if (tid == 0) {
        unsigned int v;
        do {
            asm volatile("ld.acquire.gpu.global.u32 %0, [%1];"
                         : "=r"(v) : "l"(&g_done[b]) : "memory");
            if (v < (unsigned)TPB_) __nanosleep(128);
        } while (v < (unsigned)TPB_);
    }
    __syncthreads();   // publishes tables AND the acquire to all threads

    // Phase B.
    const int c4   = tid & 31;
    const int slot = tid >> 5;
    const int oct  = (tid >> 3) & 3;
    const int res  = (slot + oct) & 7;
    const float4* __restrict__ feat =
        reinterpret_cast<const float4*>(g_nhwc) +
        (size_t)b * HW_ * (C_ / 4) + half * 32 + c4;

#pragma unroll
    for (int t = 0; t < 6; ++t) {
        const int bin = 8 * t + res;   // always < 48: guard-free
        const float4 acc = bin_taps(bin, feat, sy0, sy1, sx0, sx1,
                                    sly, shy, slx, shx);
        const int base = (4 * c4) * 49 + bin;   // conflict-free STS
        pooled[base]       = acc.x * 0.25f;
        pooled[base + 49]  = acc.y * 0.25f;
        pooled[base + 98]  = acc.z * 0.25f;
        pooled[base + 147] = acc.w * 0.25f;
    }
    if (res == 0) {
        const float4 acc = bin_taps(48, feat, sy0, sy1, sx0, sx1,
                                    sly, shy, slx, shx);
        const int base = (4 * c4) * 49 + 48;
        pooled[base]       = acc.x * 0.25f;
        pooled[base + 49]  = acc.y * 0.25f;
        pooled[base + 98]  = acc.z * 0.25f;
        pooled[base + 147] = acc.w * 0.25f;
    }
    __syncthreads();

    // Phase C: register-staged streaming fan-out.
    const float4* __restrict__ psrc = reinterpret_cast<const float4*>(pooled);
    float4 stage[RPT_];
#pragma unroll
    for (int k = 0; k < RPT_; ++k) {
        const int idx = tid + k * 256;
        if (idx < NV_) stage[k] = psrc[idx];
    }

    float4* outv = reinterpret_cast<float4*>(out);
    const int hoff = half * NV_;

    if (m < N_) {
#pragma unroll 1
        for (int q = 0; q < N_ - 1; ++q) {
            int p, slot_o;
            const int hi = N_ - 1 - m;
            if (q < hi) {
                const int j = m + 1 + q;
                p = m * (N_ - 1) - (m * (m - 1)) / 2 + (j - m - 1);
                slot_o = 0;
            } else {
                const int i = q - hi;
                p = i * (N_ - 1) - (i * (i - 1)) / 2 + (m - i - 1);
                slot_o = 1;
            }
            float4* dst = outv + (((size_t)b * P_ + p) * 3 + slot_o) * (CH_ / 4) + hoff;
#pragma unroll
            for (int k = 0; k < RPT_; ++k) {
                const int idx = tid + k * 256;
                if (idx < NV_) stcs4(&dst[idx], stage[k]);
            }
        }
    } else {
        const int p = m - N_;
        float4* dst = outv + (((size_t)b * P_ + p) * 3 + 2) * (CH_ / 4) + hoff;
#pragma unroll
        for (int k = 0; k < RPT_; ++k) {
            const int idx = tid + k * 256;
            if (idx < NV_) stcs4(&dst[idx], stage[k]);
        }
    }
}

// ---------------------------------------------------------------------------
// Cleanup: re-zero the per-batch counters so the next graph replay starts
// from a clean state (first run starts clean via static zero-init).
// ---------------------------------------------------------------------------
__global__ void cleanup_kernel() {
    if (threadIdx.x < B_) g_done[threadIdx.x] = 0u;
}

// ---------------------------------------------------------------------------
extern "C" void kernel_launch(void* const* d_in, const int* in_sizes, int n_in,
                              void* d_out, int out_size) {
    const float* features = (const float*)d_in[0];  // [B,C,H,W] float32
    const float* boxes    = (const float*)d_in[1];  // [B,N,4]   float32
    float* out = (float*)d_out;

    fused_kernel<<<NT_ + NR_, 256>>>(features, boxes, out);
    cleanup_kernel<<<1, 32>>>();
}

// round 16
// speedup vs baseline: 1.2141x; 1.2141x over previous
#include <cuda_runtime.h>
#include <cstdint>

// Problem constants
#define B_   4
#define N_   24
#define C_   256
#define H_   100
#define W_   100
#define OUT_ 7
#define P_   276                      // N*(N-1)/2
#define CH_  (C_ * OUT_ * OUT_)       // 12544 floats per full [C,7,7] chunk
#define HCH_ (CH_ / 2)                // 6272 floats per half-channel chunk
#define HW_  (H_ * W_)
#define SCALE_ 0.25f
#define NROIS_ (N_ + P_)              // 300 rois per batch
#define NV_   (HCH_ / 4)              // 1568 float4 per half tile
#define RPT_  7                       // ceil(1568/256) staging slots
#define HWT_  313                     // ceil(HW/32)

// NHWC scratch for features
__device__ float g_nhwc[(size_t)B_ * HW_ * C_];

__device__ __forceinline__ void stcs4(float4* p, float4 v) {
    asm volatile("st.global.cs.v4.f32 [%0], {%1,%2,%3,%4};"
                 :: "l"(p), "f"(v.x), "f"(v.y), "f"(v.z), "f"(v.w) : "memory");
}

// ---------------------------------------------------------------------------
// Kernel 1: per-batch NCHW -> NHWC transpose (own occupancy, unconstrained).
// ---------------------------------------------------------------------------
__global__ void nchw_to_nhwc_kernel(const float* __restrict__ in, int b) {
    __shared__ float tile[32][33];
    const int c0  = blockIdx.y * 32;
    const int hw0 = blockIdx.x * 32;
    const int tx = threadIdx.x, ty = threadIdx.y;   // (32, 8)
    const int tid = ty * 32 + tx;

    const float* src = in + (size_t)b * C_ * HW_;
#pragma unroll
    for (int i = 0; i < 32; i += 8) {
        const int c  = c0 + ty + i;
        const int hw = hw0 + tx;
        float v = 0.0f;
        if (hw < HW_) v = src[(size_t)c * HW_ + hw];
        tile[ty + i][tx] = v;
    }
    __syncthreads();

    const int tx8 = tid & 7;     // float4 channel group
    const int tyy = tid >> 3;    // hw within tile
    const int hw  = hw0 + tyy;
    if (hw < HW_) {
        float4 v;
        v.x = tile[4 * tx8 + 0][tyy];
        v.y = tile[4 * tx8 + 1][tyy];
        v.z = tile[4 * tx8 + 2][tyy];
        v.w = tile[4 * tx8 + 3][tyy];
        float* dst = g_nhwc + (size_t)b * HW_ * C_;
        *reinterpret_cast<float4*>(&dst[(size_t)hw * C_ + c0 + 4 * tx8]) = v;
    }
}

// ---------------------------------------------------------------------------
// Phase-B helper: one bin; all 16 taps loaded into locals first (MLP 16).
// ---------------------------------------------------------------------------
__device__ __forceinline__ float4 bin_taps(
    int bin, const float4* __restrict__ feat,
    const int* sy0, const int* sy1, const int* sx0, const int* sx1,
    const float* sly, const float* shy, const float* slx, const float* shx)
{
    const int py = bin / OUT_;
    const int px = bin - py * OUT_;

    int   rows[4];  float wy[4];
    int   cols[4];  float wx[4];
#pragma unroll
    for (int s = 0; s < 2; ++s) {
        const int yi = 2 * py + s;
        rows[2 * s]     = sy0[yi] * W_;
        rows[2 * s + 1] = sy1[yi] * W_;
        wy[2 * s]       = shy[yi];
        wy[2 * s + 1]   = sly[yi];
        const int xi = 2 * px + s;
        cols[2 * s]     = sx0[xi];
        cols[2 * s + 1] = sx1[xi];
        wx[2 * s]       = shx[xi];
        wx[2 * s + 1]   = slx[xi];
    }

    float4 f[16];
#pragma unroll
    for (int ys = 0; ys < 2; ++ys)
#pragma unroll
        for (int yt = 0; yt < 2; ++yt)
#pragma unroll
            for (int xs = 0; xs < 2; ++xs)
#pragma unroll
                for (int xt = 0; xt < 2; ++xt)
                    f[((ys * 2 + yt) * 2 + xs) * 2 + xt] =
                        feat[(size_t)(rows[2 * ys + yt] + cols[2 * xs + xt]) * 64];

    float4 acc = make_float4(0.f, 0.f, 0.f, 0.f);
#pragma unroll
    for (int ys = 0; ys < 2; ++ys)
#pragma unroll
        for (int yt = 0; yt < 2; ++yt)
#pragma unroll
            for (int xs = 0; xs < 2; ++xs)
#pragma unroll
                for (int xt = 0; xt < 2; ++xt) {
                    const float w = wy[2 * ys + yt] * wx[2 * xs + xt];
                    const float4 v = f[((ys * 2 + yt) * 2 + xs) * 2 + xt];
                    acc.x += w * v.x;
                    acc.y += w * v.y;
                    acc.z += w * v.z;
                    acc.w += w * v.w;
                }
    return acc;
}

// ---------------------------------------------------------------------------
// Kernel 2: per-batch roi. Grid 600 = 2 CTAs per roi (objects m<24 first).
// Identical Phase B/C to the proven R14 kernel.
// ---------------------------------------------------------------------------
__global__ __launch_bounds__(256, 3) void roi_pair_kernel(
    const float* __restrict__ boxes,   // [B, N, 4]
    float* __restrict__ out,           // [B*P, 3, C, 7, 7]
    int b)
{
    __shared__ __align__(16) float pooled[HCH_];
    __shared__ int   sy0[14], sy1[14], sx0[14], sx1[14];
    __shared__ float sly[14], shy[14], slx[14], shx[14];

    const int local = blockIdx.x;
    const int tid   = threadIdx.x;
    const int m     = local >> 1;    // 0..299: <N_ object, else union m-N_
    const int half  = local & 1;

    if (tid < 28) {
        float x1, y1, x2, y2;
        if (m < N_) {
            const float* bx = boxes + ((size_t)b * N_ + m) * 4;
            x1 = bx[0]; y1 = bx[1]; x2 = bx[2]; y2 = bx[3];
        } else {
            int p = m - N_;
            int i = 0, rem2 = p, cnt = N_ - 1;
            while (rem2 >= cnt) { rem2 -= cnt; ++i; --cnt; }
            const int j = i + 1 + rem2;
            const float* ba = boxes + ((size_t)b * N_ + i) * 4;
            const float* bb = boxes + ((size_t)b * N_ + j) * 4;
            x1 = fminf(ba[0], bb[0]);
            y1 = fminf(ba[1], bb[1]);
            x2 = fmaxf(ba[2], bb[2]);
            y2 = fmaxf(ba[3], bb[3]);
        }
        const int  d   = tid % 14;
        const bool isY = (tid >= 14);
        const float c1 = (isY ? y1 : x1) * SCALE_;
        const float c2 = (isY ? y2 : x2) * SCALE_;
        const float sz  = fmaxf(c2 - c1, 1.0f);
        const float bsz = sz * (1.0f / OUT_);
        const float g = (float)(d >> 1) + ((float)(d & 1) + 0.5f) * 0.5f;
        const float X = c1 + g * bsz;
        const int   lim = isY ? H_ : W_;
        const bool  valid = (X > -1.0f) && (X < (float)lim);
        const float Xc  = fminf(fmaxf(X, 0.0f), (float)(lim - 1));
        const float x0f = floorf(Xc);
        float lx = Xc - x0f;
        float hx = 1.0f - lx;
        if (!valid) { lx = 0.0f; hx = 0.0f; }
        const int t0 = (int)x0f;
        const int t1 = min(t0 + 1, lim - 1);
        if (isY) { sy0[d] = t0; sy1[d] = t1; sly[d] = lx; shy[d] = hx; }
        else     { sx0[d] = t0; sx1[d] = t1; slx[d] = lx; shx[d] = hx; }
    }
    __syncthreads();

    // Phase B.
    const int c4   = tid & 31;
    const int slot = tid >> 5;
    const int oct  = (tid >> 3) & 3;
    const int res  = (slot + oct) & 7;
    const float4* __restrict__ feat =
        reinterpret_cast<const float4*>(g_nhwc) +
        (size_t)b * HW_ * (C_ / 4) + half * 32 + c4;

#pragma unroll
    for (int t = 0; t < 6; ++t) {
        const int bin = 8 * t + res;   // always < 48: guard-free
        const float4 acc = bin_taps(bin, feat, sy0, sy1, sx0, sx1,
                                    sly, shy, slx, shx);
        const int base = (4 * c4) * 49 + bin;   // conflict-free STS
        pooled[base]       = acc.x * 0.25f;
        pooled[base + 49]  = acc.y * 0.25f;
        pooled[base + 98]  = acc.z * 0.25f;
        pooled[base + 147] = acc.w * 0.25f;
    }
    if (res == 0) {
        const float4 acc = bin_taps(48, feat, sy0, sy1, sx0, sx1,
                                    sly, shy, slx, shx);
        const int base = (4 * c4) * 49 + 48;
        pooled[base]       = acc.x * 0.25f;
        pooled[base + 49]  = acc.y * 0.25f;
        pooled[base + 98]  = acc.z * 0.25f;
        pooled[base + 147] = acc.w * 0.25f;
    }
    __syncthreads();

    // Phase C: register-staged streaming fan-out.
    const float4* __restrict__ psrc = reinterpret_cast<const float4*>(pooled);
    float4 stage[RPT_];
#pragma unroll
    for (int k = 0; k < RPT_; ++k) {
        const int idx = tid + k * 256;
        if (idx < NV_) stage[k] = psrc[idx];
    }

    float4* outv = reinterpret_cast<float4*>(out);
    const int hoff = half * NV_;

    if (m < N_) {
#pragma unroll 1
        for (int q = 0; q < N_ - 1; ++q) {
            int p, slot_o;
            const int hi = N_ - 1 - m;
            if (q < hi) {
                const int j = m + 1 + q;
                p = m * (N_ - 1) - (m * (m - 1)) / 2 + (j - m - 1);
                slot_o = 0;
            } else {
                const int i = q - hi;
                p = i * (N_ - 1) - (i * (i - 1)) / 2 + (m - i - 1);
                slot_o = 1;
            }
            float4* dst = outv + (((size_t)b * P_ + p) * 3 + slot_o) * (CH_ / 4) + hoff;
#pragma unroll
            for (int k = 0; k < RPT_; ++k) {
                const int idx = tid + k * 256;
                if (idx < NV_) stcs4(&dst[idx], stage[k]);
            }
        }
    } else {
        const int p = m - N_;
        float4* dst = outv + (((size_t)b * P_ + p) * 3 + 2) * (CH_ / 4) + hoff;
#pragma unroll
        for (int k = 0; k < RPT_; ++k) {
            const int idx = tid + k * 256;
            if (idx < NV_) stcs4(&dst[idx], stage[k]);
        }
    }
}

// ---------------------------------------------------------------------------
// Pipelined launch: T(b) on the origin stream; roi(b) waits only on evT[b],
// alternating between two side streams so partial-wave tails overlap.
// All cross-stream deps are events -> pure graph edges under capture.
// ---------------------------------------------------------------------------
extern "C" void kernel_launch(void* const* d_in, const int* in_sizes, int n_in,
                              void* d_out, int out_size) {
    const float* features = (const float*)d_in[0];  // [B,C,H,W] float32
    const float* boxes    = (const float*)d_in[1];  // [B,N,4]   float32
    float* out = (float*)d_out;

    static cudaStream_t sA = nullptr, sB = nullptr;
    static cudaEvent_t evT[B_], evJA, evJB;
    if (sA == nullptr) {
        cudaStreamCreateWithFlags(&sA, cudaStreamNonBlocking);
        cudaStreamCreateWithFlags(&sB, cudaStreamNonBlocking);
        for (int i = 0; i < B_; ++i)
            cudaEventCreateWithFlags(&evT[i], cudaEventDisableTiming);
        cudaEventCreateWithFlags(&evJA, cudaEventDisableTiming);
        cudaEventCreateWithFlags(&evJB, cudaEventDisableTiming);
    }

    const dim3 tgrid(HWT_, C_ / 32);
    for (int b = 0; b < B_; ++b) {
        nchw_to_nhwc_kernel<<<tgrid, dim3(32, 8)>>>(features, b);
        cudaEventRecord(evT[b], 0);
    }

    cudaStreamWaitEvent(sA, evT[0], 0);
    roi_pair_kernel<<<2 * NROIS_, 256, 0, sA>>>(boxes, out, 0);
    cudaStreamWaitEvent(sB, evT[1], 0);
    roi_pair_kernel<<<2 * NROIS_, 256, 0, sB>>>(boxes, out, 1);
    cudaStreamWaitEvent(sA, evT[2], 0);
    roi_pair_kernel<<<2 * NROIS_, 256, 0, sA>>>(boxes, out, 2);
    cudaStreamWaitEvent(sB, evT[3], 0);
    roi_pair_kernel<<<2 * NROIS_, 256, 0, sB>>>(boxes, out, 3);

    cudaEventRecord(evJA, sA);
    cudaEventRecord(evJB, sB);
    cudaStreamWaitEvent(0, evJA, 0);
    cudaStreamWaitEvent(0, evJB, 0);
}

// round 17
// speedup vs baseline: 1.3496x; 1.1116x over previous
#include <cuda_runtime.h>
#include <cstdint>

// Problem constants
#define B_   4
#define N_   24
#define C_   256
#define H_   100
#define W_   100
#define OUT_ 7
#define P_   276                      // N*(N-1)/2
#define CH_  (C_ * OUT_ * OUT_)       // 12544 floats per full [C,7,7] chunk
#define HCH_ (CH_ / 2)                // 6272 floats per half-channel chunk
#define HW_  (H_ * W_)
#define SCALE_ 0.25f
#define NROIS_ (N_ + P_)              // 300 rois per batch
#define NV_   (HCH_ / 4)              // 1568 float4 per half tile
#define RPT_  7                       // ceil(1568/256) staging slots
#define HWT128_ 79                    // ceil(HW/128) hw tiles (128-wide)

// NHWC scratch for features
__device__ float g_nhwc[(size_t)B_ * HW_ * C_];

__device__ __forceinline__ void stcs4(float4* p, float4 v) {
    asm volatile("st.global.cs.v4.f32 [%0], {%1,%2,%3,%4};"
                 :: "l"(p), "f"(v.x), "f"(v.y), "f"(v.z), "f"(v.w) : "memory");
}

// ---------------------------------------------------------------------------
// Kernel 1: NCHW -> NHWC transpose, v2.
// Tile = 32 channels x 128 hw. Load side: float4 along hw (LDG.128, MLP 16
// per thread). smem float4[32][32] with XOR swizzle j^c: conflict-free STS.128
// writes AND conflict-free scalar reads (bank = 4(j^c) + lane>>3, all
// distinct per warp). Store side: float4 along c, 4x128B segments per warp.
// ---------------------------------------------------------------------------
__global__ void nchw_to_nhwc_kernel(const float* __restrict__ in) {
    __shared__ float4 tile4[32][32];
    const int b   = blockIdx.z;
    const int c0  = blockIdx.y * 32;
    const int hw0 = blockIdx.x * 128;
    const int tid = threadIdx.x;            // 256

    // Load: c = (tid>>5)+8i, lane covers 128 hw as 32 float4.
    {
        const int lane = tid & 31;
        const int cb   = tid >> 5;          // 0..7
        const int hw   = hw0 + 4 * lane;
        const float* src = in + (size_t)b * C_ * HW_;
#pragma unroll
        for (int i = 0; i < 4; ++i) {
            const int c = cb + 8 * i;       // 0..31 local
            float4 v = make_float4(0.f, 0.f, 0.f, 0.f);
            if (hw < HW_)                   // HW%4==0 -> hw+3 < HW too
                v = *reinterpret_cast<const float4*>(
                        &src[(size_t)(c0 + c) * HW_ + hw]);
            tile4[c][lane ^ c] = v;
        }
    }
    __syncthreads();

    // Store: thread -> (cg = tid&7 channel quad, hw_local = (tid>>3)+32j).
    {
        const int cg = tid & 7;
        float* dst = g_nhwc + (size_t)b * HW_ * C_;
#pragma unroll
        for (int j = 0; j < 4; ++j) {
            const int hw_local = (tid >> 3) + 32 * j;   // 0..127
            const int hw = hw0 + hw_local;
            if (hw < HW_) {
                const int j4   = hw_local >> 2;
                const int comp = hw_local & 3;
                float4 v;
                {
                    const float* t0 = reinterpret_cast<const float*>(&tile4[4*cg+0][j4 ^ (4*cg+0)]);
                    const float* t1 = reinterpret_cast<const float*>(&tile4[4*cg+1][j4 ^ (4*cg+1)]);
                    const float* t2 = reinterpret_cast<const float*>(&tile4[4*cg+2][j4 ^ (4*cg+2)]);
                    const float* t3 = reinterpret_cast<const float*>(&tile4[4*cg+3][j4 ^ (4*cg+3)]);
                    v.x = t0[comp]; v.y = t1[comp]; v.z = t2[comp]; v.w = t3[comp];
                }
                *reinterpret_cast<float4*>(&dst[(size_t)hw * C_ + c0 + 4 * cg]) = v;
            }
        }
    }
}

// ---------------------------------------------------------------------------
// Phase-B helper: one bin; all 16 taps loaded into locals first (MLP 16).
// ---------------------------------------------------------------------------
__device__ __forceinline__ float4 bin_taps(
    int bin, const float4* __restrict__ feat,
    const int* sy0, const int* sy1, const int* sx0, const int* sx1,
    const float* sly, const float* shy, const float* slx, const float* shx)
{
    const int py = bin / OUT_;
    const int px = bin - py * OUT_;

    int   rows[4];  float wy[4];
    int   cols[4];  float wx[4];
#pragma unroll
    for (int s = 0; s < 2; ++s) {
        const int yi = 2 * py + s;
        rows[2 * s]     = sy0[yi] * W_;
        rows[2 * s + 1] = sy1[yi] * W_;
        wy[2 * s]       = shy[yi];
        wy[2 * s + 1]   = sly[yi];
        const int xi = 2 * px + s;
        cols[2 * s]     = sx0[xi];
        cols[2 * s + 1] = sx1[xi];
        wx[2 * s]       = shx[xi];
        wx[2 * s + 1]   = slx[xi];
    }

    float4 f[16];
#pragma unroll
    for (int ys = 0; ys < 2; ++ys)
#pragma unroll
        for (int yt = 0; yt < 2; ++yt)
#pragma unroll
            for (int xs = 0; xs < 2; ++xs)
#pragma unroll
                for (int xt = 0; xt < 2; ++xt)
                    f[((ys * 2 + yt) * 2 + xs) * 2 + xt] =
                        feat[(size_t)(rows[2 * ys + yt] + cols[2 * xs + xt]) * 64];

    float4 acc = make_float4(0.f, 0.f, 0.f, 0.f);
#pragma unroll
    for (int ys = 0; ys < 2; ++ys)
#pragma unroll
        for (int yt = 0; yt < 2; ++yt)
#pragma unroll
            for (int xs = 0; xs < 2; ++xs)
#pragma unroll
                for (int xt = 0; xt < 2; ++xt) {
                    const float w = wy[2 * ys + yt] * wx[2 * xs + xt];
                    const float4 v = f[((ys * 2 + yt) * 2 + xs) * 2 + xt];
                    acc.x += w * v.x;
                    acc.y += w * v.y;
                    acc.z += w * v.z;
                    acc.w += w * v.w;
                }
    return acc;
}

// ---------------------------------------------------------------------------
// Kernel 2: TWO CTAs per roi (one per 128-channel half). 256 threads.
// Identical to the proven R14 kernel.
// ---------------------------------------------------------------------------
__global__ __launch_bounds__(256, 3) void roi_pair_kernel(
    const float* __restrict__ boxes,   // [B, N, 4] xyxy, image coords
    float* __restrict__ out)           // [B*P, 3, C, 7, 7]
{
    __shared__ __align__(16) float pooled[HCH_];
    __shared__ int   sy0[14], sy1[14], sx0[14], sx1[14];
    __shared__ float sly[14], shy[14], slx[14], shx[14];

    const int bid  = blockIdx.x;
    const int tid  = threadIdx.x;
    const int r    = bid >> 1;       // roi id 0..1199 (objects first)
    const int half = bid & 1;        // channel half

    int b, m;  // batch, roi index within batch (m < N_: object, else union)
    if (r < B_ * N_) { b = r / N_; m = r % N_; }
    else { const int u = r - B_ * N_; b = u / P_; m = N_ + (u % P_); }

    if (tid < 28) {
        float x1, y1, x2, y2;
        if (m < N_) {
            const float* bx = boxes + ((size_t)b * N_ + m) * 4;
            x1 = bx[0]; y1 = bx[1]; x2 = bx[2]; y2 = bx[3];
        } else {
            int p = m - N_;
            int i = 0, rem = p, cnt = N_ - 1;
            while (rem >= cnt) { rem -= cnt; ++i; --cnt; }
            const int j = i + 1 + rem;
            const float* ba = boxes + ((size_t)b * N_ + i) * 4;
            const float* bb = boxes + ((size_t)b * N_ + j) * 4;
            x1 = fminf(ba[0], bb[0]);
            y1 = fminf(ba[1], bb[1]);
            x2 = fmaxf(ba[2], bb[2]);
            y2 = fmaxf(ba[3], bb[3]);
        }
        const int  d   = tid % 14;
        const bool isY = (tid >= 14);
        const float c1 = (isY ? y1 : x1) * SCALE_;
        const float c2 = (isY ? y2 : x2) * SCALE_;
        const float sz  = fmaxf(c2 - c1, 1.0f);
        const float bsz = sz * (1.0f / OUT_);
        const float g = (float)(d >> 1) + ((float)(d & 1) + 0.5f) * 0.5f;
        const float X = c1 + g * bsz;
        const int   lim = isY ? H_ : W_;
        const bool  valid = (X > -1.0f) && (X < (float)lim);
        const float Xc  = fminf(fmaxf(X, 0.0f), (float)(lim - 1));
        const float x0f = floorf(Xc);
        float lx = Xc - x0f;
        float hx = 1.0f - lx;
        if (!valid) { lx = 0.0f; hx = 0.0f; }
        const int t0 = (int)x0f;
        const int t1 = min(t0 + 1, lim - 1);
        if (isY) { sy0[d] = t0; sy1[d] = t1; sly[d] = lx; shy[d] = hx; }
        else     { sx0[d] = t0; sx1[d] = t1; slx[d] = lx; shx[d] = hx; }
    }
    __syncthreads();

    // Phase B.
    const int c4   = tid & 31;
    const int slot = tid >> 5;
    const int oct  = (tid >> 3) & 3;
    const int res  = (slot + oct) & 7;
    const float4* __restrict__ feat =
        reinterpret_cast<const float4*>(g_nhwc) +
        (size_t)b * HW_ * (C_ / 4) + half * 32 + c4;

#pragma unroll
    for (int t = 0; t < 6; ++t) {
        const int bin = 8 * t + res;   // always < 48: guard-free
        const float4 acc = bin_taps(bin, feat, sy0, sy1, sx0, sx1,
                                    sly, shy, slx, shx);
        const int base = (4 * c4) * 49 + bin;   // conflict-free STS
        pooled[base]       = acc.x * 0.25f;
        pooled[base + 49]  = acc.y * 0.25f;
        pooled[base + 98]  = acc.z * 0.25f;
        pooled[base + 147] = acc.w * 0.25f;
    }
    if (res == 0) {
        const float4 acc = bin_taps(48, feat, sy0, sy1, sx0, sx1,
                                    sly, shy, slx, shx);
        const int base = (4 * c4) * 49 + 48;
        pooled[base]       = acc.x * 0.25f;
        pooled[base + 49]  = acc.y * 0.25f;
        pooled[base + 98]  = acc.z * 0.25f;
        pooled[base + 147] = acc.w * 0.25f;
    }
    __syncthreads();

    // Phase C: register-staged streaming fan-out.
    const float4* __restrict__ psrc = reinterpret_cast<const float4*>(pooled);
    float4 stage[RPT_];
#pragma unroll
    for (int k = 0; k < RPT_; ++k) {
        const int idx = tid + k * 256;
        if (idx < NV_) stage[k] = psrc[idx];
    }

    float4* outv = reinterpret_cast<float4*>(out);
    const int hoff = half * NV_;

    if (m < N_) {
#pragma unroll 1
        for (int q = 0; q < N_ - 1; ++q) {
            int p, slot_o;
            const int hi = N_ - 1 - m;
            if (q < hi) {
                const int j = m + 1 + q;
                p = m * (N_ - 1) - (m * (m - 1)) / 2 + (j - m - 1);
                slot_o = 0;
            } else {
                const int i = q - hi;
                p = i * (N_ - 1) - (i * (i - 1)) / 2 + (m - i - 1);
                slot_o = 1;
            }
            float4* dst = outv + (((size_t)b * P_ + p) * 3 + slot_o) * (CH_ / 4) + hoff;
#pragma unroll
            for (int k = 0; k < RPT_; ++k) {
                const int idx = tid + k * 256;
                if (idx < NV_) stcs4(&dst[idx], stage[k]);
            }
        }
    } else {
        const int p = m - N_;
        float4* dst = outv + (((size_t)b * P_ + p) * 3 + 2) * (CH_ / 4) + hoff;
#pragma unroll
        for (int k = 0; k < RPT_; ++k) {
            const int idx = tid + k * 256;
            if (idx < NV_) stcs4(&dst[idx], stage[k]);
        }
    }
}

// ---------------------------------------------------------------------------
extern "C" void kernel_launch(void* const* d_in, const int* in_sizes, int n_in,
                              void* d_out, int out_size) {
    const float* features = (const float*)d_in[0];  // [B,C,H,W] float32
    const float* boxes    = (const float*)d_in[1];  // [B,N,4]   float32
    float* out = (float*)d_out;

    dim3 tgrid(HWT128_, C_ / 32, B_);   // 79 x 8 x 4 = 2528 CTAs
    nchw_to_nhwc_kernel<<<tgrid, 256>>>(features);

    const int nblocks = 2 * B_ * NROIS_;   // 2400: 192 object CTAs first
    roi_pair_kernel<<<nblocks, 256>>>(boxes, out);
}